// round 7
// baseline (speedup 1.0000x reference)
#include <cuda_runtime.h>
#include <math.h>

#define FD 256
#define MAXN 200000
#define MAXB 4096

// scratch (static __device__ — no allocations)
__device__ __align__(16) float g_buf1[(size_t)MAXN * FD];
__device__ __align__(16) float g_buf2[(size_t)MAXN * FD];
__device__ float g_s[MAXN];
__device__ float g_a[MAXN];
__device__ float g_anorm[MAXB];
__device__ float g_cb[MAXB];
__device__ float g_eb[MAXB];
__device__ __align__(16) float g_w[FD];
__device__ float g_b0;

__device__ __forceinline__ float siluf(float x) {
    return x * (1.0f / (1.0f + __expf(-x)));
}

// w[j] = sum_i Wq[i,j] * Wk[i];  b0 = sum_i bq[i]*Wk[i]
__global__ void prep_w_kernel(const float* __restrict__ Wq,
                              const float* __restrict__ bq,
                              const float* __restrict__ Wk) {
    int j = threadIdx.x;  // 256 threads
    float acc = 0.f;
    #pragma unroll 4
    for (int i = 0; i < FD; i++) acc = fmaf(Wq[i * FD + j], Wk[i], acc);
    g_w[j] = acc;
    __shared__ float sh[FD];
    sh[j] = bq[j] * Wk[j];
    __syncthreads();
    for (int st = FD / 2; st > 0; st >>= 1) {
        if (j < st) sh[j] += sh[j + st];
        __syncthreads();
    }
    if (j == 0) g_b0 = sh[0];
}

__global__ void prep_batch_kernel(const float* __restrict__ E, int B) {
    int b = blockIdx.x * blockDim.x + threadIdx.x;
    if (b < B) {
        float e = fabsf(E[b]);
        g_eb[b] = e;
        g_cb[b] = e / fmaxf(e, 1.0f);
    }
}

// per-atom: dot = x_n . w ; a = softplus(cb * (dot + b0) / 16)
__global__ void attn_kernel(const float* __restrict__ x,
                            const int* __restrict__ seg, int M) {
    int warp = (blockIdx.x * blockDim.x + threadIdx.x) >> 5;
    int lane = threadIdx.x & 31;
    if (warp >= M) return;
    const float4* xr = (const float4*)(x + (size_t)warp * FD);
    const float4* wr = (const float4*)g_w;
    float acc = 0.f;
    #pragma unroll
    for (int i = 0; i < 2; i++) {
        float4 a = xr[lane + 32 * i];
        float4 w = wr[lane + 32 * i];
        acc += a.x * w.x + a.y * w.y + a.z * w.z + a.w * w.w;
    }
    #pragma unroll
    for (int o = 16; o > 0; o >>= 1) acc += __shfl_xor_sync(0xffffffffu, acc, o);
    if (lane == 0) {
        int b = seg[warp];
        float t = g_cb[b] * (acc + g_b0) * 0.0625f;  // /sqrt(256)
        // stable softplus = max(t,0) + log1p(exp(-|t|))
        g_a[warp] = fmaxf(t, 0.f) + log1pf(expf(-fabsf(t)));
    }
}

// deterministic segment sum (batch_seg is sorted): warp per batch, binary search range
__global__ void anorm_kernel(const int* __restrict__ seg, int M, int B) {
    int b = (blockIdx.x * blockDim.x + threadIdx.x) >> 5;
    int lane = threadIdx.x & 31;
    if (b >= B) return;
    int lo = 0, hi = M;
    while (lo < hi) { int mid = (lo + hi) >> 1; if (seg[mid] < b) lo = mid + 1; else hi = mid; }
    int start = lo;
    hi = M;
    while (lo < hi) { int mid = (lo + hi) >> 1; if (seg[mid] < b + 1) lo = mid + 1; else hi = mid; }
    int end = lo;
    float acc = 0.f;
    for (int i = start + lane; i < end; i += 32) acc += g_a[i];
    #pragma unroll
    for (int o = 16; o > 0; o >>= 1) acc += __shfl_xor_sync(0xffffffffu, acc, o);
    if (lane == 0) g_anorm[b] = acc;
}

__global__ void s_kernel(const int* __restrict__ seg, int M) {
    int n = blockIdx.x * blockDim.x + threadIdx.x;
    if (n < M) {
        int b = seg[n];
        g_s[n] = g_a[n] * g_eb[b] / (g_anorm[b] + 1e-8f);
    }
}

// =====================  GEMM: C[n,j] = sum_k silu(A[n,k]) * W[j,k] (+res) =====================
// aSel: 0 = A generated as y[n,k] = s_n * Wv[k]; 1 = g_buf1; 2 = g_buf2
// resSel: 0 none; 1 = y (s_n * Wv[j]); 2 = g_buf2
// outSel: 1 = g_buf1; 2 = g_buf2; 3 = Cext
#define BM 128
#define BN 128
#define BK 16
#define PAD 4

__global__ __launch_bounds__(256, 2) void gemm_kernel(
    const float* __restrict__ W, float* __restrict__ Cext,
    const float* __restrict__ Wv, int M, int aSel, int resSel, int outSel) {
    __shared__ float As[BK][BM + PAD];
    __shared__ float Bs[BK][BN + PAD];
    const int tid = threadIdx.x;
    const int row0 = blockIdx.x * BM;
    const int col0 = blockIdx.y * BN;
    const int tx = tid & 15;
    const int ty = tid >> 4;

    const float* __restrict__ A = (aSel == 1) ? g_buf1 : g_buf2;
    float* __restrict__ C = (outSel == 1) ? g_buf1 : (outSel == 2 ? g_buf2 : Cext);

    float acc[8][8];
    #pragma unroll
    for (int i = 0; i < 8; i++)
        #pragma unroll
        for (int j = 0; j < 8; j++) acc[i][j] = 0.f;

    const int q0 = tid, q1 = tid + 256;
    const int ar0 = q0 >> 2, ac0 = (q0 & 3) * 4;
    const int ar1 = q1 >> 2, ac1 = (q1 & 3) * 4;
    const bool v0 = (row0 + ar0) < M, v1 = (row0 + ar1) < M;
    float s0 = 0.f, s1 = 0.f;
    if (aSel == 0) {
        if (v0) s0 = g_s[row0 + ar0];
        if (v1) s1 = g_s[row0 + ar1];
    }

    const float* __restrict__ Arow0 = A + (size_t)(row0 + ar0) * FD + ac0;
    const float* __restrict__ Arow1 = A + (size_t)(row0 + ar1) * FD + ac1;
    const float* __restrict__ Wrow0 = W + (size_t)(col0 + ar0) * FD + ac0;
    const float* __restrict__ Wrow1 = W + (size_t)(col0 + ar1) * FD + ac1;

    for (int k0 = 0; k0 < FD; k0 += BK) {
        float4 a0, a1;
        if (aSel == 0) {
            const float* __restrict__ wv = Wv + k0;
            a0 = make_float4(s0 * wv[ac0], s0 * wv[ac0 + 1], s0 * wv[ac0 + 2], s0 * wv[ac0 + 3]);
            a1 = make_float4(s1 * wv[ac1], s1 * wv[ac1 + 1], s1 * wv[ac1 + 2], s1 * wv[ac1 + 3]);
        } else {
            a0 = v0 ? *(const float4*)(Arow0 + k0) : make_float4(0.f, 0.f, 0.f, 0.f);
            a1 = v1 ? *(const float4*)(Arow1 + k0) : make_float4(0.f, 0.f, 0.f, 0.f);
        }
        As[ac0 + 0][ar0] = siluf(a0.x); As[ac0 + 1][ar0] = siluf(a0.y);
        As[ac0 + 2][ar0] = siluf(a0.z); As[ac0 + 3][ar0] = siluf(a0.w);
        As[ac1 + 0][ar1] = siluf(a1.x); As[ac1 + 1][ar1] = siluf(a1.y);
        As[ac1 + 2][ar1] = siluf(a1.z); As[ac1 + 3][ar1] = siluf(a1.w);

        float4 b0v = *(const float4*)(Wrow0 + k0);
        float4 b1v = *(const float4*)(Wrow1 + k0);
        Bs[ac0 + 0][ar0] = b0v.x; Bs[ac0 + 1][ar0] = b0v.y;
        Bs[ac0 + 2][ar0] = b0v.z; Bs[ac0 + 3][ar0] = b0v.w;
        Bs[ac1 + 0][ar1] = b1v.x; Bs[ac1 + 1][ar1] = b1v.y;
        Bs[ac1 + 2][ar1] = b1v.z; Bs[ac1 + 3][ar1] = b1v.w;
        __syncthreads();

        #pragma unroll
        for (int k = 0; k < BK; k++) {
            float4 ra0 = *(const float4*)&As[k][ty * 4];
            float4 ra1 = *(const float4*)&As[k][64 + ty * 4];
            float4 rb0 = *(const float4*)&Bs[k][tx * 4];
            float4 rb1 = *(const float4*)&Bs[k][64 + tx * 4];
            float ra[8] = {ra0.x, ra0.y, ra0.z, ra0.w, ra1.x, ra1.y, ra1.z, ra1.w};
            float rb[8] = {rb0.x, rb0.y, rb0.z, rb0.w, rb1.x, rb1.y, rb1.z, rb1.w};
            #pragma unroll
            for (int i = 0; i < 8; i++)
                #pragma unroll
                for (int j = 0; j < 8; j++) acc[i][j] = fmaf(ra[i], rb[j], acc[i][j]);
        }
        __syncthreads();
    }

    // epilogue: rows split {ty*4+i, 64+ty*4+i}, cols split {tx*4.., 64+tx*4..}
    #pragma unroll
    for (int i = 0; i < 8; i++) {
        int gr = row0 + ((i < 4) ? (ty * 4 + i) : (64 + ty * 4 + i - 4));
        if (gr >= M) continue;
        float sv = (resSel == 1) ? g_s[gr] : 0.f;
        #pragma unroll
        for (int g = 0; g < 2; g++) {
            int gc = col0 + g * 64 + tx * 4;
            int jb = g * 4;
            float4 r = make_float4(0.f, 0.f, 0.f, 0.f);
            if (resSel == 1) {
                r.x = sv * Wv[gc]; r.y = sv * Wv[gc + 1];
                r.z = sv * Wv[gc + 2]; r.w = sv * Wv[gc + 3];
            } else if (resSel == 2) {
                r = *(const float4*)(g_buf2 + (size_t)gr * FD + gc);
            }
            float4 o = make_float4(acc[i][jb] + r.x, acc[i][jb + 1] + r.y,
                                   acc[i][jb + 2] + r.z, acc[i][jb + 3] + r.w);
            *(float4*)(C + (size_t)gr * FD + gc) = o;
        }
    }
}

extern "C" void kernel_launch(void* const* d_in, const int* in_sizes, int n_in,
                              void* d_out, int out_size) {
    const float* x = (const float*)d_in[0];
    const float* E = (const float*)d_in[1];
    // d_in[2] = num_batch (unused; B from in_sizes[1])
    const int* seg = (const int*)d_in[3];   // int32 (JAX x64 disabled)
    const float* Wq = (const float*)d_in[4];
    const float* bq = (const float*)d_in[5];
    const float* Wk = (const float*)d_in[6];
    const float* Wv = (const float*)d_in[7];
    const float* Wres1 = (const float*)d_in[8];
    const float* Wres2 = (const float*)d_in[9];
    const float* Wout = (const float*)d_in[10];
    float* out = (float*)d_out;

    const int M = in_sizes[0] / FD;
    const int B = in_sizes[1];
    const int R = in_sizes[8] / (FD * FD);

    prep_w_kernel<<<1, 256>>>(Wq, bq, Wk);
    prep_batch_kernel<<<(B + 255) / 256, 256>>>(E, B);
    attn_kernel<<<(M + 7) / 8, 256>>>(x, seg, M);
    anorm_kernel<<<(B * 32 + 255) / 256, 256>>>(seg, M, B);
    s_kernel<<<(M + 255) / 256, 256>>>(seg, M);

    dim3 grid((M + BM - 1) / BM, FD / BN);
    int aSel = 0;  // h starts as virtual y = s ⊗ Wv
    for (int r = 0; r < R; r++) {
        // buf1 = silu(h) @ Wres1[r].T
        gemm_kernel<<<grid, 256>>>(Wres1 + (size_t)r * FD * FD, nullptr, Wv, M,
                                   aSel, 0, 1);
        // buf2 = silu(buf1) @ Wres2[r].T + h
        gemm_kernel<<<grid, 256>>>(Wres2 + (size_t)r * FD * FD, nullptr, Wv, M,
                                   1, (aSel == 0) ? 1 : 2, 2);
        aSel = 2;
    }
    // out = silu(h) @ Wout.T
    gemm_kernel<<<grid, 256>>>(Wout, out, Wv, M, 2, 0, 3);
}

// round 15
// speedup vs baseline: 8.6714x; 8.6714x over previous
#include <cuda_runtime.h>
#include <stdint.h>
#include <math.h>

#define FD 256
#define MAXN 200000
#define MAXB 4096
#define NODES 8192

// scratch (static __device__ — no allocations)
__device__ __align__(16) float g_buf1[(size_t)NODES * FD];
__device__ __align__(16) float g_buf2[(size_t)NODES * FD];
__device__ __align__(16) float g_table[(size_t)NODES * FD];
__device__ float g_ns[NODES];
__device__ float g_s[MAXN];
__device__ float g_a[MAXN];
__device__ float g_anorm[MAXB];
__device__ float g_cb[MAXB];
__device__ float g_eb[MAXB];
__device__ __align__(16) float g_w[FD];
__device__ float g_b0;
__device__ unsigned int g_minenc;
__device__ unsigned int g_maxenc;
__device__ float g_lo;
__device__ float g_idelta;

__device__ __forceinline__ float siluf(float x) {
    return x * (1.0f / (1.0f + __expf(-x)));
}

// monotone encode/decode for float atomic min/max (total order, sign-safe)
__device__ __forceinline__ unsigned int fenc(float f) {
    unsigned int u = __float_as_uint(f);
    return (u & 0x80000000u) ? ~u : (u | 0x80000000u);
}
__device__ __forceinline__ float fdec(unsigned int u) {
    return __uint_as_float((u & 0x80000000u) ? (u & 0x7FFFFFFFu) : ~u);
}

// w[j] = sum_i Wq[i,j] * Wk[i];  b0 = sum_i bq[i]*Wk[i]; also init min/max
__global__ void prep_w_kernel(const float* __restrict__ Wq,
                              const float* __restrict__ bq,
                              const float* __restrict__ Wk) {
    int j = threadIdx.x;  // 256 threads
    if (j == 0) { g_minenc = 0xFFFFFFFFu; g_maxenc = 0u; }
    float acc = 0.f;
    #pragma unroll 4
    for (int i = 0; i < FD; i++) acc = fmaf(Wq[i * FD + j], Wk[i], acc);
    g_w[j] = acc;
    __shared__ float sh[FD];
    sh[j] = bq[j] * Wk[j];
    __syncthreads();
    for (int st = FD / 2; st > 0; st >>= 1) {
        if (j < st) sh[j] += sh[j + st];
        __syncthreads();
    }
    if (j == 0) g_b0 = sh[0];
}

__global__ void prep_batch_kernel(const float* __restrict__ E, int B) {
    int b = blockIdx.x * blockDim.x + threadIdx.x;
    if (b < B) {
        float e = fabsf(E[b]);
        g_eb[b] = e;
        g_cb[b] = e / fmaxf(e, 1.0f);
    }
}

// per-atom: dot = x_n . w ; a = softplus(cb * (dot + b0) / 16)
__global__ void attn_kernel(const float* __restrict__ x,
                            const int* __restrict__ seg, int M) {
    int warp = (blockIdx.x * blockDim.x + threadIdx.x) >> 5;
    int lane = threadIdx.x & 31;
    if (warp >= M) return;
    const float4* xr = (const float4*)(x + (size_t)warp * FD);
    const float4* wr = (const float4*)g_w;
    float acc = 0.f;
    #pragma unroll
    for (int i = 0; i < 2; i++) {
        float4 a = xr[lane + 32 * i];
        float4 w = wr[lane + 32 * i];
        acc += a.x * w.x + a.y * w.y + a.z * w.z + a.w * w.w;
    }
    #pragma unroll
    for (int o = 16; o > 0; o >>= 1) acc += __shfl_xor_sync(0xffffffffu, acc, o);
    if (lane == 0) {
        int b = seg[warp];
        float t = g_cb[b] * (acc + g_b0) * 0.0625f;  // /sqrt(256)
        g_a[warp] = fmaxf(t, 0.f) + log1pf(expf(-fabsf(t)));
    }
}

// deterministic segment sum (batch_seg is sorted): warp per batch, binary search
__global__ void anorm_kernel(const int* __restrict__ seg, int M, int B) {
    int b = (blockIdx.x * blockDim.x + threadIdx.x) >> 5;
    int lane = threadIdx.x & 31;
    if (b >= B) return;
    int lo = 0, hi = M;
    while (lo < hi) { int mid = (lo + hi) >> 1; if (seg[mid] < b) lo = mid + 1; else hi = mid; }
    int start = lo;
    hi = M;
    while (lo < hi) { int mid = (lo + hi) >> 1; if (seg[mid] < b + 1) lo = mid + 1; else hi = mid; }
    int end = lo;
    float acc = 0.f;
    for (int i = start + lane; i < end; i += 32) acc += g_a[i];
    #pragma unroll
    for (int o = 16; o > 0; o >>= 1) acc += __shfl_xor_sync(0xffffffffu, acc, o);
    if (lane == 0) g_anorm[b] = acc;
}

__global__ void s_kernel(const int* __restrict__ seg, int M) {
    int n = blockIdx.x * blockDim.x + threadIdx.x;
    if (n < M) {
        int b = seg[n];
        g_s[n] = g_a[n] * g_eb[b] / (g_anorm[b] + 1e-8f);
    }
}

// block-reduce min/max of g_s, then one atomicMin/Max per block (deterministic)
__global__ void minmax_kernel(int M) {
    __shared__ unsigned int smin[256], smax[256];
    int t = threadIdx.x;
    int n = blockIdx.x * blockDim.x + t;
    unsigned int mn = 0xFFFFFFFFu, mx = 0u;
    for (int i = n; i < M; i += gridDim.x * blockDim.x) {
        unsigned int e = fenc(g_s[i]);
        mn = min(mn, e); mx = max(mx, e);
    }
    smin[t] = mn; smax[t] = mx;
    __syncthreads();
    for (int st = 128; st > 0; st >>= 1) {
        if (t < st) {
            smin[t] = min(smin[t], smin[t + st]);
            smax[t] = max(smax[t], smax[t + st]);
        }
        __syncthreads();
    }
    if (t == 0) {
        atomicMin(&g_minenc, smin[0]);
        atomicMax(&g_maxenc, smax[0]);
    }
}

// build node grid: g_ns[i] = lo + i*delta; publish lo, 1/delta
__global__ void node_kernel() {
    float lo = fdec(g_minenc);
    float hi = fdec(g_maxenc);
    float span = hi - lo;
    float delta = span / (float)(NODES - 1);
    int i = blockIdx.x * blockDim.x + threadIdx.x;
    if (i < NODES) g_ns[i] = lo + delta * (float)i;
    if (i == 0) {
        g_lo = lo;
        g_idelta = (span > 1e-30f) ? (1.0f / delta) : 0.0f;
    }
}

// =====================  GEMM: C[n,j] = sum_k silu(A[n,k]) * W[j,k] (+res) ===================
// proven R7 kernel, generalized: s-array select (0=g_s, 1=g_ns), outSel 4 = g_table
// aSel: 0 = A generated as y[n,k] = s_n * Wv[k]; 1 = g_buf1; 2 = g_buf2
// resSel: 0 none; 1 = y (s_n * Wv[j]); 2 = g_buf2
// outSel: 1 = g_buf1; 2 = g_buf2; 4 = g_table
#define BM 128
#define BN 128
#define BK 16
#define PAD 4

__global__ __launch_bounds__(256, 2) void gemm_kernel(
    const float* __restrict__ W, const float* __restrict__ Wv,
    int M, int aSel, int resSel, int outSel, int sSel) {
    __shared__ float As[BK][BM + PAD];
    __shared__ float Bs[BK][BN + PAD];
    const int tid = threadIdx.x;
    const int row0 = blockIdx.x * BM;
    const int col0 = blockIdx.y * BN;
    const int tx = tid & 15;
    const int ty = tid >> 4;

    const float* __restrict__ sp = (sSel == 0) ? g_s : g_ns;
    const float* __restrict__ A = (aSel == 1) ? g_buf1 : g_buf2;
    float* __restrict__ C = (outSel == 1) ? g_buf1 : (outSel == 2 ? g_buf2 : g_table);

    float acc[8][8];
    #pragma unroll
    for (int i = 0; i < 8; i++)
        #pragma unroll
        for (int j = 0; j < 8; j++) acc[i][j] = 0.f;

    const int q0 = tid, q1 = tid + 256;
    const int ar0 = q0 >> 2, ac0 = (q0 & 3) * 4;
    const int ar1 = q1 >> 2, ac1 = (q1 & 3) * 4;
    const bool v0 = (row0 + ar0) < M, v1 = (row0 + ar1) < M;
    float s0 = 0.f, s1 = 0.f;
    if (aSel == 0) {
        if (v0) s0 = sp[row0 + ar0];
        if (v1) s1 = sp[row0 + ar1];
    }

    const float* __restrict__ Arow0 = A + (size_t)(row0 + ar0) * FD + ac0;
    const float* __restrict__ Arow1 = A + (size_t)(row0 + ar1) * FD + ac1;
    const float* __restrict__ Wrow0 = W + (size_t)(col0 + ar0) * FD + ac0;
    const float* __restrict__ Wrow1 = W + (size_t)(col0 + ar1) * FD + ac1;

    for (int k0 = 0; k0 < FD; k0 += BK) {
        float4 a0, a1;
        if (aSel == 0) {
            const float* __restrict__ wv = Wv + k0;
            a0 = make_float4(s0 * wv[ac0], s0 * wv[ac0 + 1], s0 * wv[ac0 + 2], s0 * wv[ac0 + 3]);
            a1 = make_float4(s1 * wv[ac1], s1 * wv[ac1 + 1], s1 * wv[ac1 + 2], s1 * wv[ac1 + 3]);
        } else {
            a0 = v0 ? *(const float4*)(Arow0 + k0) : make_float4(0.f, 0.f, 0.f, 0.f);
            a1 = v1 ? *(const float4*)(Arow1 + k0) : make_float4(0.f, 0.f, 0.f, 0.f);
        }
        As[ac0 + 0][ar0] = siluf(a0.x); As[ac0 + 1][ar0] = siluf(a0.y);
        As[ac0 + 2][ar0] = siluf(a0.z); As[ac0 + 3][ar0] = siluf(a0.w);
        As[ac1 + 0][ar1] = siluf(a1.x); As[ac1 + 1][ar1] = siluf(a1.y);
        As[ac1 + 2][ar1] = siluf(a1.z); As[ac1 + 3][ar1] = siluf(a1.w);

        float4 b0v = *(const float4*)(Wrow0 + k0);
        float4 b1v = *(const float4*)(Wrow1 + k0);
        Bs[ac0 + 0][ar0] = b0v.x; Bs[ac0 + 1][ar0] = b0v.y;
        Bs[ac0 + 2][ar0] = b0v.z; Bs[ac0 + 3][ar0] = b0v.w;
        Bs[ac1 + 0][ar1] = b1v.x; Bs[ac1 + 1][ar1] = b1v.y;
        Bs[ac1 + 2][ar1] = b1v.z; Bs[ac1 + 3][ar1] = b1v.w;
        __syncthreads();

        #pragma unroll
        for (int k = 0; k < BK; k++) {
            float4 ra0 = *(const float4*)&As[k][ty * 4];
            float4 ra1 = *(const float4*)&As[k][64 + ty * 4];
            float4 rb0 = *(const float4*)&Bs[k][tx * 4];
            float4 rb1 = *(const float4*)&Bs[k][64 + tx * 4];
            float ra[8] = {ra0.x, ra0.y, ra0.z, ra0.w, ra1.x, ra1.y, ra1.z, ra1.w};
            float rb[8] = {rb0.x, rb0.y, rb0.z, rb0.w, rb1.x, rb1.y, rb1.z, rb1.w};
            #pragma unroll
            for (int i = 0; i < 8; i++)
                #pragma unroll
                for (int j = 0; j < 8; j++) acc[i][j] = fmaf(ra[i], rb[j], acc[i][j]);
        }
        __syncthreads();
    }

    #pragma unroll
    for (int i = 0; i < 8; i++) {
        int gr = row0 + ((i < 4) ? (ty * 4 + i) : (64 + ty * 4 + i - 4));
        if (gr >= M) continue;
        float sv = (resSel == 1) ? sp[gr] : 0.f;
        #pragma unroll
        for (int g = 0; g < 2; g++) {
            int gc = col0 + g * 64 + tx * 4;
            int jb = g * 4;
            float4 r = make_float4(0.f, 0.f, 0.f, 0.f);
            if (resSel == 1) {
                r.x = sv * Wv[gc]; r.y = sv * Wv[gc + 1];
                r.z = sv * Wv[gc + 2]; r.w = sv * Wv[gc + 3];
            } else if (resSel == 2) {
                r = *(const float4*)(g_buf2 + (size_t)gr * FD + gc);
            }
            float4 o = make_float4(acc[i][jb] + r.x, acc[i][jb + 1] + r.y,
                                   acc[i][jb + 2] + r.z, acc[i][jb + 3] + r.w);
            *(float4*)(C + (size_t)gr * FD + gc) = o;
        }
    }
}

// ================= Catmull-Rom interpolation: out[n,:] = G(s_n) from node table ============
// warp per atom; lane covers 8 cols (2 float4)
__global__ __launch_bounds__(256) void interp_kernel(float* __restrict__ out, int M) {
    int atom = blockIdx.x * 8 + (threadIdx.x >> 5);
    int lane = threadIdx.x & 31;
    if (atom >= M) return;
    float u = (g_s[atom] - g_lo) * g_idelta;
    u = fminf(fmaxf(u, 0.f), (float)(NODES - 1));
    int i1 = (int)u;
    if (i1 > NODES - 1) i1 = NODES - 1;
    float t = u - (float)i1;
    int i0 = max(i1 - 1, 0);
    int i2 = min(i1 + 1, NODES - 1);
    int i3 = min(i1 + 2, NODES - 1);
    float t2 = t * t, t3 = t2 * t;
    float c0 = 0.5f * (-t3 + 2.f * t2 - t);
    float c1 = 0.5f * (3.f * t3 - 5.f * t2 + 2.f);
    float c2 = 0.5f * (-3.f * t3 + 4.f * t2 + t);
    float c3 = 0.5f * (t3 - t2);
    const float* p0 = g_table + (size_t)i0 * FD + lane * 8;
    const float* p1 = g_table + (size_t)i1 * FD + lane * 8;
    const float* p2 = g_table + (size_t)i2 * FD + lane * 8;
    const float* p3 = g_table + (size_t)i3 * FD + lane * 8;
    float* o = out + (size_t)atom * FD + lane * 8;
    #pragma unroll
    for (int h = 0; h < 2; h++) {
        float4 a = *(const float4*)(p0 + h * 4);
        float4 b = *(const float4*)(p1 + h * 4);
        float4 cc = *(const float4*)(p2 + h * 4);
        float4 d = *(const float4*)(p3 + h * 4);
        float4 r;
        r.x = c0 * a.x + c1 * b.x + c2 * cc.x + c3 * d.x;
        r.y = c0 * a.y + c1 * b.y + c2 * cc.y + c3 * d.y;
        r.z = c0 * a.z + c1 * b.z + c2 * cc.z + c3 * d.z;
        r.w = c0 * a.w + c1 * b.w + c2 * cc.w + c3 * d.w;
        *(float4*)(o + h * 4) = r;
    }
}

extern "C" void kernel_launch(void* const* d_in, const int* in_sizes, int n_in,
                              void* d_out, int out_size) {
    const float* x = (const float*)d_in[0];
    const float* E = (const float*)d_in[1];
    // d_in[2] = num_batch (unused; B from in_sizes[1])
    const int* seg = (const int*)d_in[3];   // int32 (JAX x64 disabled)
    const float* Wq = (const float*)d_in[4];
    const float* bq = (const float*)d_in[5];
    const float* Wk = (const float*)d_in[6];
    const float* Wv = (const float*)d_in[7];
    const float* Wres1 = (const float*)d_in[8];
    const float* Wres2 = (const float*)d_in[9];
    const float* Wout = (const float*)d_in[10];
    float* out = (float*)d_out;

    const int M = in_sizes[0] / FD;
    const int B = in_sizes[1];
    const int R = in_sizes[8] / (FD * FD);

    // ---- per-atom scalar s_n (exact) ----
    prep_w_kernel<<<1, 256>>>(Wq, bq, Wk);
    prep_batch_kernel<<<(B + 255) / 256, 256>>>(E, B);
    attn_kernel<<<(M + 7) / 8, 256>>>(x, seg, M);
    anorm_kernel<<<(B * 32 + 255) / 256, 256>>>(seg, M, B);
    s_kernel<<<(M + 255) / 256, 256>>>(seg, M);

    // ---- node grid over [smin, smax] ----
    minmax_kernel<<<148, 256>>>(M);
    node_kernel<<<NODES / 256, 256>>>();

    // ---- exact G at NODES points via proven fp32 GEMM chain (sSel=1 -> g_ns) ----
    dim3 grid((NODES + BM - 1) / BM, FD / BN);
    int aSel = 0;  // h starts as virtual y = s ⊗ Wv
    for (int r = 0; r < R; r++) {
        gemm_kernel<<<grid, 256>>>(Wres1 + (size_t)r * FD * FD, Wv, NODES, aSel, 0, 1, 1);
        gemm_kernel<<<grid, 256>>>(Wres2 + (size_t)r * FD * FD, Wv, NODES, 1,
                                   (aSel == 0) ? 1 : 2, 2, 1);
        aSel = 2;
    }
    gemm_kernel<<<grid, 256>>>(Wout, Wv, NODES, 2, 0, 4, 1);

    // ---- cubic interpolation to all atoms ----
    interp_kernel<<<(M + 7) / 8, 256>>>(out, M);
}

// round 16
// speedup vs baseline: 9.9924x; 1.1523x over previous
#include <cuda_runtime.h>
#include <stdint.h>
#include <math.h>

#define FD 256
#define MAXN 200000
#define MAXB 4096
#define NODES 4096

// scratch (static __device__ — no allocations). Pair buffers for split-K partials.
__device__ __align__(16) float g_buf1a[(size_t)NODES * FD];
__device__ __align__(16) float g_buf1b[(size_t)NODES * FD];
__device__ __align__(16) float g_buf2a[(size_t)NODES * FD];
__device__ __align__(16) float g_buf2b[(size_t)NODES * FD];
__device__ __align__(16) float g_buf3a[(size_t)NODES * FD];
__device__ __align__(16) float g_buf3b[(size_t)NODES * FD];
__device__ __align__(16) float g_tablea[(size_t)NODES * FD];
__device__ __align__(16) float g_tableb[(size_t)NODES * FD];
__device__ float g_ns[NODES];
__device__ float g_s[MAXN];
__device__ float g_a[MAXN];
__device__ float g_anorm[MAXB];
__device__ float g_cb[MAXB];
__device__ float g_eb[MAXB];
__device__ __align__(16) float g_w[FD];
__device__ float g_b0;
__device__ unsigned int g_minenc;
__device__ unsigned int g_maxenc;
__device__ float g_lo;
__device__ float g_idelta;

__device__ __forceinline__ float siluf(float x) {
    return x * (1.0f / (1.0f + __expf(-x)));
}

// monotone encode/decode for float atomic min/max (total order, sign-safe)
__device__ __forceinline__ unsigned int fenc(float f) {
    unsigned int u = __float_as_uint(f);
    return (u & 0x80000000u) ? ~u : (u | 0x80000000u);
}
__device__ __forceinline__ float fdec(unsigned int u) {
    return __uint_as_float((u & 0x80000000u) ? (u & 0x7FFFFFFFu) : ~u);
}

// w[j] = sum_i Wq[i,j] * Wk[i];  b0 = sum_i bq[i]*Wk[i]; also init min/max
__global__ void prep_w_kernel(const float* __restrict__ Wq,
                              const float* __restrict__ bq,
                              const float* __restrict__ Wk) {
    int j = threadIdx.x;  // 256 threads
    if (j == 0) { g_minenc = 0xFFFFFFFFu; g_maxenc = 0u; }
    float acc = 0.f;
    #pragma unroll 4
    for (int i = 0; i < FD; i++) acc = fmaf(Wq[i * FD + j], Wk[i], acc);
    g_w[j] = acc;
    __shared__ float sh[FD];
    sh[j] = bq[j] * Wk[j];
    __syncthreads();
    for (int st = FD / 2; st > 0; st >>= 1) {
        if (j < st) sh[j] += sh[j + st];
        __syncthreads();
    }
    if (j == 0) g_b0 = sh[0];
}

__global__ void prep_batch_kernel(const float* __restrict__ E, int B) {
    int b = blockIdx.x * blockDim.x + threadIdx.x;
    if (b < B) {
        float e = fabsf(E[b]);
        g_eb[b] = e;
        g_cb[b] = e / fmaxf(e, 1.0f);
    }
}

// per-atom: dot = x_n . w ; a = softplus(cb * (dot + b0) / 16)
__global__ void attn_kernel(const float* __restrict__ x,
                            const int* __restrict__ seg, int M) {
    int warp = (blockIdx.x * blockDim.x + threadIdx.x) >> 5;
    int lane = threadIdx.x & 31;
    if (warp >= M) return;
    const float4* xr = (const float4*)(x + (size_t)warp * FD);
    const float4* wr = (const float4*)g_w;
    float acc = 0.f;
    #pragma unroll
    for (int i = 0; i < 2; i++) {
        float4 a = xr[lane + 32 * i];
        float4 w = wr[lane + 32 * i];
        acc += a.x * w.x + a.y * w.y + a.z * w.z + a.w * w.w;
    }
    #pragma unroll
    for (int o = 16; o > 0; o >>= 1) acc += __shfl_xor_sync(0xffffffffu, acc, o);
    if (lane == 0) {
        int b = seg[warp];
        float t = g_cb[b] * (acc + g_b0) * 0.0625f;  // /sqrt(256)
        g_a[warp] = fmaxf(t, 0.f) + log1pf(expf(-fabsf(t)));
    }
}

// deterministic segment sum (batch_seg is sorted): warp per batch, binary search
__global__ void anorm_kernel(const int* __restrict__ seg, int M, int B) {
    int b = (blockIdx.x * blockDim.x + threadIdx.x) >> 5;
    int lane = threadIdx.x & 31;
    if (b >= B) return;
    int lo = 0, hi = M;
    while (lo < hi) { int mid = (lo + hi) >> 1; if (seg[mid] < b) lo = mid + 1; else hi = mid; }
    int start = lo;
    hi = M;
    while (lo < hi) { int mid = (lo + hi) >> 1; if (seg[mid] < b + 1) lo = mid + 1; else hi = mid; }
    int end = lo;
    float acc = 0.f;
    for (int i = start + lane; i < end; i += 32) acc += g_a[i];
    #pragma unroll
    for (int o = 16; o > 0; o >>= 1) acc += __shfl_xor_sync(0xffffffffu, acc, o);
    if (lane == 0) g_anorm[b] = acc;
}

__global__ void s_kernel(const int* __restrict__ seg, int M) {
    int n = blockIdx.x * blockDim.x + threadIdx.x;
    if (n < M) {
        int b = seg[n];
        g_s[n] = g_a[n] * g_eb[b] / (g_anorm[b] + 1e-8f);
    }
}

// block-reduce min/max of g_s, then one atomicMin/Max per block (deterministic)
__global__ void minmax_kernel(int M) {
    __shared__ unsigned int smin[256], smax[256];
    int t = threadIdx.x;
    int n = blockIdx.x * blockDim.x + t;
    unsigned int mn = 0xFFFFFFFFu, mx = 0u;
    for (int i = n; i < M; i += gridDim.x * blockDim.x) {
        unsigned int e = fenc(g_s[i]);
        mn = min(mn, e); mx = max(mx, e);
    }
    smin[t] = mn; smax[t] = mx;
    __syncthreads();
    for (int st = 128; st > 0; st >>= 1) {
        if (t < st) {
            smin[t] = min(smin[t], smin[t + st]);
            smax[t] = max(smax[t], smax[t + st]);
        }
        __syncthreads();
    }
    if (t == 0) {
        atomicMin(&g_minenc, smin[0]);
        atomicMax(&g_maxenc, smax[0]);
    }
}

// build node grid: g_ns[i] = lo + i*delta; publish lo, 1/delta
__global__ void node_kernel() {
    float lo = fdec(g_minenc);
    float hi = fdec(g_maxenc);
    float span = hi - lo;
    float delta = span / (float)(NODES - 1);
    int i = blockIdx.x * blockDim.x + threadIdx.x;
    if (i < NODES) g_ns[i] = lo + delta * (float)i;
    if (i == 0) {
        g_lo = lo;
        g_idelta = (span > 1e-30f) ? (1.0f / delta) : 0.0f;
    }
}

// ===========  split-K GEMM: C_z[n,j] = sum_{k in half z} silu(A(n,k)) * W[j,k] (+res@z0) ====
// A(n,k): aSel 0 = s_n*Wv[k] (virtual); 1 = buf1a+buf1b; 2 = buf2a+buf2b; 3 = buf3a+buf3b
// resSel (z==0 only): 0 none; 1 = s_n*Wv[j]; 2 = buf2 pair; 3 = buf3 pair
// outSel: 1 = buf1 pair; 2 = buf2 pair; 3 = buf3 pair; 4 = table pair  (split z writes [z])
#define BM 128
#define BN 128
#define BK 16
#define PAD 4
#define KSPLIT 128

__global__ __launch_bounds__(256, 2) void gemm_kernel(
    const float* __restrict__ W, const float* __restrict__ Wv,
    int M, int aSel, int resSel, int outSel) {
    __shared__ float As[BK][BM + PAD];
    __shared__ float Bs[BK][BN + PAD];
    const int tid = threadIdx.x;
    const int row0 = blockIdx.x * BM;
    const int col0 = blockIdx.y * BN;
    const int z = blockIdx.z;
    const int kbase = z * KSPLIT;
    const int tx = tid & 15;
    const int ty = tid >> 4;

    const float* __restrict__ A0 = g_buf1a;
    const float* __restrict__ A1 = g_buf1b;
    if (aSel == 2) { A0 = g_buf2a; A1 = g_buf2b; }
    else if (aSel == 3) { A0 = g_buf3a; A1 = g_buf3b; }
    float* __restrict__ C;
    switch (outSel) {
        case 1: C = z ? g_buf1b : g_buf1a; break;
        case 2: C = z ? g_buf2b : g_buf2a; break;
        case 3: C = z ? g_buf3b : g_buf3a; break;
        default: C = z ? g_tableb : g_tablea; break;
    }

    float acc[8][8];
    #pragma unroll
    for (int i = 0; i < 8; i++)
        #pragma unroll
        for (int j = 0; j < 8; j++) acc[i][j] = 0.f;

    const int q0 = tid, q1 = tid + 256;
    const int ar0 = q0 >> 2, ac0 = (q0 & 3) * 4;
    const int ar1 = q1 >> 2, ac1 = (q1 & 3) * 4;
    const bool v0 = (row0 + ar0) < M, v1 = (row0 + ar1) < M;
    float s0 = 0.f, s1 = 0.f;
    if (aSel == 0) {
        if (v0) s0 = g_ns[row0 + ar0];
        if (v1) s1 = g_ns[row0 + ar1];
    }

    const size_t aoff0 = (size_t)(row0 + ar0) * FD + ac0;
    const size_t aoff1 = (size_t)(row0 + ar1) * FD + ac1;
    const float* __restrict__ Wrow0 = W + (size_t)(col0 + ar0) * FD + ac0;
    const float* __restrict__ Wrow1 = W + (size_t)(col0 + ar1) * FD + ac1;

    for (int kk = 0; kk < KSPLIT; kk += BK) {
        const int k0 = kbase + kk;
        float4 a0, a1;
        if (aSel == 0) {
            const float* __restrict__ wv = Wv + k0;
            a0 = make_float4(s0 * wv[ac0], s0 * wv[ac0 + 1], s0 * wv[ac0 + 2], s0 * wv[ac0 + 3]);
            a1 = make_float4(s1 * wv[ac1], s1 * wv[ac1 + 1], s1 * wv[ac1 + 2], s1 * wv[ac1 + 3]);
        } else {
            a0 = make_float4(0.f, 0.f, 0.f, 0.f);
            a1 = make_float4(0.f, 0.f, 0.f, 0.f);
            if (v0) {
                float4 p = *(const float4*)(A0 + aoff0 + k0);
                float4 q = *(const float4*)(A1 + aoff0 + k0);
                a0 = make_float4(p.x + q.x, p.y + q.y, p.z + q.z, p.w + q.w);
            }
            if (v1) {
                float4 p = *(const float4*)(A0 + aoff1 + k0);
                float4 q = *(const float4*)(A1 + aoff1 + k0);
                a1 = make_float4(p.x + q.x, p.y + q.y, p.z + q.z, p.w + q.w);
            }
        }
        As[ac0 + 0][ar0] = siluf(a0.x); As[ac0 + 1][ar0] = siluf(a0.y);
        As[ac0 + 2][ar0] = siluf(a0.z); As[ac0 + 3][ar0] = siluf(a0.w);
        As[ac1 + 0][ar1] = siluf(a1.x); As[ac1 + 1][ar1] = siluf(a1.y);
        As[ac1 + 2][ar1] = siluf(a1.z); As[ac1 + 3][ar1] = siluf(a1.w);

        float4 b0v = *(const float4*)(Wrow0 + k0);
        float4 b1v = *(const float4*)(Wrow1 + k0);
        Bs[ac0 + 0][ar0] = b0v.x; Bs[ac0 + 1][ar0] = b0v.y;
        Bs[ac0 + 2][ar0] = b0v.z; Bs[ac0 + 3][ar0] = b0v.w;
        Bs[ac1 + 0][ar1] = b1v.x; Bs[ac1 + 1][ar1] = b1v.y;
        Bs[ac1 + 2][ar1] = b1v.z; Bs[ac1 + 3][ar1] = b1v.w;
        __syncthreads();

        #pragma unroll
        for (int k = 0; k < BK; k++) {
            float4 ra0 = *(const float4*)&As[k][ty * 4];
            float4 ra1 = *(const float4*)&As[k][64 + ty * 4];
            float4 rb0 = *(const float4*)&Bs[k][tx * 4];
            float4 rb1 = *(const float4*)&Bs[k][64 + tx * 4];
            float ra[8] = {ra0.x, ra0.y, ra0.z, ra0.w, ra1.x, ra1.y, ra1.z, ra1.w};
            float rb[8] = {rb0.x, rb0.y, rb0.z, rb0.w, rb1.x, rb1.y, rb1.z, rb1.w};
            #pragma unroll
            for (int i = 0; i < 8; i++)
                #pragma unroll
                for (int j = 0; j < 8; j++) acc[i][j] = fmaf(ra[i], rb[j], acc[i][j]);
        }
        __syncthreads();
    }

    const float* __restrict__ R0 = (resSel == 3) ? g_buf3a : g_buf2a;
    const float* __restrict__ R1 = (resSel == 3) ? g_buf3b : g_buf2b;

    #pragma unroll
    for (int i = 0; i < 8; i++) {
        int gr = row0 + ((i < 4) ? (ty * 4 + i) : (64 + ty * 4 + i - 4));
        if (gr >= M) continue;
        float sv = (resSel == 1 && z == 0) ? g_ns[gr] : 0.f;
        #pragma unroll
        for (int g = 0; g < 2; g++) {
            int gc = col0 + g * 64 + tx * 4;
            int jb = g * 4;
            float4 r = make_float4(0.f, 0.f, 0.f, 0.f);
            if (z == 0) {
                if (resSel == 1) {
                    r.x = sv * Wv[gc]; r.y = sv * Wv[gc + 1];
                    r.z = sv * Wv[gc + 2]; r.w = sv * Wv[gc + 3];
                } else if (resSel >= 2) {
                    float4 p = *(const float4*)(R0 + (size_t)gr * FD + gc);
                    float4 q = *(const float4*)(R1 + (size_t)gr * FD + gc);
                    r = make_float4(p.x + q.x, p.y + q.y, p.z + q.z, p.w + q.w);
                }
            }
            float4 o = make_float4(acc[i][jb] + r.x, acc[i][jb + 1] + r.y,
                                   acc[i][jb + 2] + r.z, acc[i][jb + 3] + r.w);
            *(float4*)(C + (size_t)gr * FD + gc) = o;
        }
    }
}

// ======= Catmull-Rom interpolation: out[n,:] = G(s_n) from summed node-table pair =========
// warp per atom; lane covers 8 cols (2 float4)
__global__ __launch_bounds__(256) void interp_kernel(float* __restrict__ out, int M) {
    int atom = blockIdx.x * 8 + (threadIdx.x >> 5);
    int lane = threadIdx.x & 31;
    if (atom >= M) return;
    float u = (g_s[atom] - g_lo) * g_idelta;
    u = fminf(fmaxf(u, 0.f), (float)(NODES - 1));
    int i1 = (int)u;
    if (i1 > NODES - 1) i1 = NODES - 1;
    float t = u - (float)i1;
    int i0 = max(i1 - 1, 0);
    int i2 = min(i1 + 1, NODES - 1);
    int i3 = min(i1 + 2, NODES - 1);
    float t2 = t * t, t3 = t2 * t;
    float c0 = 0.5f * (-t3 + 2.f * t2 - t);
    float c1 = 0.5f * (3.f * t3 - 5.f * t2 + 2.f);
    float c2 = 0.5f * (-3.f * t3 + 4.f * t2 + t);
    float c3 = 0.5f * (t3 - t2);
    const size_t o0 = (size_t)i0 * FD + lane * 8;
    const size_t o1 = (size_t)i1 * FD + lane * 8;
    const size_t o2 = (size_t)i2 * FD + lane * 8;
    const size_t o3 = (size_t)i3 * FD + lane * 8;
    float* o = out + (size_t)atom * FD + lane * 8;
    #pragma unroll
    for (int h = 0; h < 2; h++) {
        float4 a0 = *(const float4*)(g_tablea + o0 + h * 4);
        float4 a1 = *(const float4*)(g_tableb + o0 + h * 4);
        float4 b0 = *(const float4*)(g_tablea + o1 + h * 4);
        float4 b1 = *(const float4*)(g_tableb + o1 + h * 4);
        float4 c0v = *(const float4*)(g_tablea + o2 + h * 4);
        float4 c1v = *(const float4*)(g_tableb + o2 + h * 4);
        float4 d0 = *(const float4*)(g_tablea + o3 + h * 4);
        float4 d1 = *(const float4*)(g_tableb + o3 + h * 4);
        float4 r;
        r.x = c0 * (a0.x + a1.x) + c1 * (b0.x + b1.x) + c2 * (c0v.x + c1v.x) + c3 * (d0.x + d1.x);
        r.y = c0 * (a0.y + a1.y) + c1 * (b0.y + b1.y) + c2 * (c0v.y + c1v.y) + c3 * (d0.y + d1.y);
        r.z = c0 * (a0.z + a1.z) + c1 * (b0.z + b1.z) + c2 * (c0v.z + c1v.z) + c3 * (d0.z + d1.z);
        r.w = c0 * (a0.w + a1.w) + c1 * (b0.w + b1.w) + c2 * (c0v.w + c1v.w) + c3 * (d0.w + d1.w);
        *(float4*)(o + h * 4) = r;
    }
}

extern "C" void kernel_launch(void* const* d_in, const int* in_sizes, int n_in,
                              void* d_out, int out_size) {
    const float* x = (const float*)d_in[0];
    const float* E = (const float*)d_in[1];
    // d_in[2] = num_batch (unused; B from in_sizes[1])
    const int* seg = (const int*)d_in[3];   // int32 (JAX x64 disabled)
    const float* Wq = (const float*)d_in[4];
    const float* bq = (const float*)d_in[5];
    const float* Wk = (const float*)d_in[6];
    const float* Wv = (const float*)d_in[7];
    const float* Wres1 = (const float*)d_in[8];
    const float* Wres2 = (const float*)d_in[9];
    const float* Wout = (const float*)d_in[10];
    float* out = (float*)d_out;

    const int M = in_sizes[0] / FD;
    const int B = in_sizes[1];
    const int R = in_sizes[8] / (FD * FD);

    // ---- per-atom scalar s_n (exact) ----
    prep_w_kernel<<<1, 256>>>(Wq, bq, Wk);
    prep_batch_kernel<<<(B + 255) / 256, 256>>>(E, B);
    attn_kernel<<<(M + 7) / 8, 256>>>(x, seg, M);
    anorm_kernel<<<(B * 32 + 255) / 256, 256>>>(seg, M, B);
    s_kernel<<<(M + 255) / 256, 256>>>(seg, M);

    // ---- node grid over [smin, smax] ----
    minmax_kernel<<<148, 256>>>(M);
    node_kernel<<<NODES / 256, 256>>>();

    // ---- exact G at NODES points via split-K fp32 GEMM chain ----
    dim3 grid(NODES / BM, FD / BN, 2);
    int aSel = 0;   // h starts as virtual y = s ⊗ Wv
    int hres = 1;   // residual selector for current h
    for (int r = 0; r < R; r++) {
        // buf1 pair = partials of silu(h) @ Wres1[r].T
        gemm_kernel<<<grid, 256>>>(Wres1 + (size_t)r * FD * FD, Wv, NODES, aSel, 0, 1);
        // hnew pair = partials of silu(t) @ Wres2[r].T + h (residual on split 0)
        int dst = (r % 2 == 0) ? 2 : 3;
        gemm_kernel<<<grid, 256>>>(Wres2 + (size_t)r * FD * FD, Wv, NODES, 1, hres, dst);
        aSel = dst;
        hres = dst;
    }
    // table pair = partials of silu(h) @ Wout.T
    gemm_kernel<<<grid, 256>>>(Wout, Wv, NODES, aSel, 0, 4);

    // ---- cubic interpolation to all atoms (sums table pair; linear => exact) ----
    interp_kernel<<<(M + 7) / 8, 256>>>(out, M);
}

// round 17
// speedup vs baseline: 12.0993x; 1.2108x over previous
#include <cuda_runtime.h>
#include <stdint.h>
#include <math.h>

#define FD 256
#define MAXN 200000
#define MAXB 4096
#define NODES 4736          // 148 SMs x 32 rows: exactly one wave of chain CTAs
#define CBM 32              // node rows per chain CTA

// scratch (static __device__ — no allocations)
__device__ __align__(16) float g_table[(size_t)NODES * FD];
__device__ float g_ns[NODES];
__device__ float g_s[MAXN];
__device__ float g_a[MAXN];
__device__ float g_anorm[MAXB];
__device__ float g_cb[MAXB];
__device__ float g_eb[MAXB];
__device__ __align__(16) float g_w[FD];
__device__ float g_b0;
__device__ unsigned int g_minenc;
__device__ unsigned int g_maxenc;
__device__ float g_lo;
__device__ float g_idelta;

__device__ __forceinline__ float siluf(float x) {
    return x * (1.0f / (1.0f + __expf(-x)));
}

// monotone encode/decode for float atomic min/max (total order, sign-safe)
__device__ __forceinline__ unsigned int fenc(float f) {
    unsigned int u = __float_as_uint(f);
    return (u & 0x80000000u) ? ~u : (u | 0x80000000u);
}
__device__ __forceinline__ float fdec(unsigned int u) {
    return __uint_as_float((u & 0x80000000u) ? (u & 0x7FFFFFFFu) : ~u);
}

// w[j] = sum_i Wq[i,j] * Wk[i];  b0 = sum_i bq[i]*Wk[i]; also init min/max
__global__ void prep_w_kernel(const float* __restrict__ Wq,
                              const float* __restrict__ bq,
                              const float* __restrict__ Wk) {
    int j = threadIdx.x;  // 256 threads
    if (j == 0) { g_minenc = 0xFFFFFFFFu; g_maxenc = 0u; }
    float acc = 0.f;
    #pragma unroll 4
    for (int i = 0; i < FD; i++) acc = fmaf(Wq[i * FD + j], Wk[i], acc);
    g_w[j] = acc;
    __shared__ float sh[FD];
    sh[j] = bq[j] * Wk[j];
    __syncthreads();
    for (int st = FD / 2; st > 0; st >>= 1) {
        if (j < st) sh[j] += sh[j + st];
        __syncthreads();
    }
    if (j == 0) g_b0 = sh[0];
}

__global__ void prep_batch_kernel(const float* __restrict__ E, int B) {
    int b = blockIdx.x * blockDim.x + threadIdx.x;
    if (b < B) {
        float e = fabsf(E[b]);
        g_eb[b] = e;
        g_cb[b] = e / fmaxf(e, 1.0f);
    }
}

// per-atom: dot = x_n . w ; a = softplus(cb * (dot + b0) / 16)
__global__ void attn_kernel(const float* __restrict__ x,
                            const int* __restrict__ seg, int M) {
    int warp = (blockIdx.x * blockDim.x + threadIdx.x) >> 5;
    int lane = threadIdx.x & 31;
    if (warp >= M) return;
    const float4* xr = (const float4*)(x + (size_t)warp * FD);
    const float4* wr = (const float4*)g_w;
    float acc = 0.f;
    #pragma unroll
    for (int i = 0; i < 2; i++) {
        float4 a = xr[lane + 32 * i];
        float4 w = wr[lane + 32 * i];
        acc += a.x * w.x + a.y * w.y + a.z * w.z + a.w * w.w;
    }
    #pragma unroll
    for (int o = 16; o > 0; o >>= 1) acc += __shfl_xor_sync(0xffffffffu, acc, o);
    if (lane == 0) {
        int b = seg[warp];
        float t = g_cb[b] * (acc + g_b0) * 0.0625f;  // /sqrt(256)
        g_a[warp] = fmaxf(t, 0.f) + log1pf(expf(-fabsf(t)));
    }
}

// deterministic segment sum (batch_seg is sorted): warp per batch, binary search
__global__ void anorm_kernel(const int* __restrict__ seg, int M, int B) {
    int b = (blockIdx.x * blockDim.x + threadIdx.x) >> 5;
    int lane = threadIdx.x & 31;
    if (b >= B) return;
    int lo = 0, hi = M;
    while (lo < hi) { int mid = (lo + hi) >> 1; if (seg[mid] < b) lo = mid + 1; else hi = mid; }
    int start = lo;
    hi = M;
    while (lo < hi) { int mid = (lo + hi) >> 1; if (seg[mid] < b + 1) lo = mid + 1; else hi = mid; }
    int end = lo;
    float acc = 0.f;
    for (int i = start + lane; i < end; i += 32) acc += g_a[i];
    #pragma unroll
    for (int o = 16; o > 0; o >>= 1) acc += __shfl_xor_sync(0xffffffffu, acc, o);
    if (lane == 0) g_anorm[b] = acc;
}

// fused: s_n = a_n * e_b / (anorm_b + eps); block-reduce min/max + one atomic pair
__global__ void s_minmax_kernel(const int* __restrict__ seg, int M) {
    __shared__ unsigned int smin[256], smax[256];
    int t = threadIdx.x;
    int n = blockIdx.x * blockDim.x + t;
    unsigned int mn = 0xFFFFFFFFu, mx = 0u;
    if (n < M) {
        int b = seg[n];
        float sval = g_a[n] * g_eb[b] / (g_anorm[b] + 1e-8f);
        g_s[n] = sval;
        unsigned int e = fenc(sval);
        mn = e; mx = e;
    }
    smin[t] = mn; smax[t] = mx;
    __syncthreads();
    for (int st = 128; st > 0; st >>= 1) {
        if (t < st) {
            smin[t] = min(smin[t], smin[t + st]);
            smax[t] = max(smax[t], smax[t + st]);
        }
        __syncthreads();
    }
    if (t == 0) {
        atomicMin(&g_minenc, smin[0]);
        atomicMax(&g_maxenc, smax[0]);
    }
}

// build node grid: g_ns[i] = lo + i*delta; publish lo, 1/delta
__global__ void node_kernel() {
    float lo = fdec(g_minenc);
    float hi = fdec(g_maxenc);
    float span = hi - lo;
    float delta = span / (float)(NODES - 1);
    int i = blockIdx.x * blockDim.x + threadIdx.x;
    if (i < NODES) g_ns[i] = lo + delta * (float)i;
    if (i == 0) {
        g_lo = lo;
        g_idelta = (span > 1e-30f) ? (1.0f / delta) : 0.0f;
    }
}

// ======================= fused whole-chain kernel =======================
// One CTA = 32 node rows through the ENTIRE network: y -> R resblocks -> out.
// smem: h[32][260] raw state, sb[32][260] = silu(state) operand, Bs dbl-buffered W tile.
// Layout: 256 threads; warp ty owns rows ty*4..ty*4+3; lane tx owns cols tx+32*jj.
// Bs stored [j][33] (stride 33 words): STS scalar conflict-free, LDS scalar conflict-free.
#define HS 260                    // h/sb row stride (floats)
#define BSS 33                    // Bs row stride (floats)
#define BSBUF (FD * BSS)          // 8448 floats per Bs buffer
#define SM_H 0
#define SM_S (CBM * HS)           // 8320
#define SM_B (2 * CBM * HS)       // 16640
#define CHAIN_SMEM ((2 * CBM * HS + 2 * BSBUF) * 4)   // 134144 bytes

// one GEMM stage: acc = silu_operand(sb) @ W^T for this CTA's 32 rows.
// mode 0: sb = silu(acc)        (t-stage)
// mode 1: h += acc; sb = silu(h) (residual stage)
// mode 2: g_table rows = acc     (output stage)
__device__ __forceinline__ void chain_stage(const float* __restrict__ W,
                                            float* sh, int mode, int row0) {
    const int tid = threadIdx.x;
    const int tx = tid & 31;
    const int ty = tid >> 5;
    const int jb = tid >> 3;       // 0..31  (W row group for loads)
    const int k4 = tid & 7;        // 0..7   (k-float4 within tile)
    float* hs = sh + SM_H;
    float* sb = sh + SM_S;

    float acc[4][8];
    #pragma unroll
    for (int i = 0; i < 4; i++)
        #pragma unroll
        for (int j = 0; j < 8; j++) acc[i][j] = 0.f;

    // prefetch tile 0: thread loads 8 rows j = jb+32m, 1 float4 along k each
    float4 reg[8];
    #pragma unroll
    for (int m = 0; m < 8; m++)
        reg[m] = *(const float4*)(W + (size_t)(jb + 32 * m) * FD + k4 * 4);

    for (int t = 0; t < 8; t++) {                 // 8 tiles of BK=32
        float* bs = sh + SM_B + (t & 1) * BSBUF;
        // STS (scalar: stride-33 rows keep banks distinct: bank = jb + 4*k4 + c)
        #pragma unroll
        for (int m = 0; m < 8; m++) {
            float* dst = bs + (jb + 32 * m) * BSS + k4 * 4;
            dst[0] = reg[m].x; dst[1] = reg[m].y; dst[2] = reg[m].z; dst[3] = reg[m].w;
        }
        __syncthreads();
        if (t < 7) {
            const float* Wn = W + (t + 1) * 32;
            #pragma unroll
            for (int m = 0; m < 8; m++)
                reg[m] = *(const float4*)(Wn + (size_t)(jb + 32 * m) * FD + k4 * 4);
        }
        // compute this tile: k = t*32 + (k4v*4 + c)
        #pragma unroll 4
        for (int k4v = 0; k4v < 8; k4v++) {
            float4 ra4[4];
            #pragma unroll
            for (int i = 0; i < 4; i++)
                ra4[i] = *(const float4*)(sb + (ty * 4 + i) * HS + t * 32 + k4v * 4);
            #pragma unroll
            for (int c = 0; c < 4; c++) {
                float ra[4] = { c == 0 ? ra4[0].x : c == 1 ? ra4[0].y : c == 2 ? ra4[0].z : ra4[0].w,
                                c == 0 ? ra4[1].x : c == 1 ? ra4[1].y : c == 2 ? ra4[1].z : ra4[1].w,
                                c == 0 ? ra4[2].x : c == 1 ? ra4[2].y : c == 2 ? ra4[2].z : ra4[2].w,
                                c == 0 ? ra4[3].x : c == 1 ? ra4[3].y : c == 2 ? ra4[3].z : ra4[3].w };
                float rb[8];
                #pragma unroll
                for (int jj = 0; jj < 8; jj++)
                    rb[jj] = bs[(tx + 32 * jj) * BSS + k4v * 4 + c];
                #pragma unroll
                for (int i = 0; i < 4; i++)
                    #pragma unroll
                    for (int jj = 0; jj < 8; jj++)
                        acc[i][jj] = fmaf(ra[i], rb[jj], acc[i][jj]);
            }
        }
    }
    __syncthreads();   // all reads of sb complete before overwrite

    if (mode == 0) {
        #pragma unroll
        for (int i = 0; i < 4; i++)
            #pragma unroll
            for (int jj = 0; jj < 8; jj++)
                sb[(ty * 4 + i) * HS + tx + 32 * jj] = siluf(acc[i][jj]);
    } else if (mode == 1) {
        #pragma unroll
        for (int i = 0; i < 4; i++)
            #pragma unroll
            for (int jj = 0; jj < 8; jj++) {
                int off = (ty * 4 + i) * HS + tx + 32 * jj;
                float nh = hs[off] + acc[i][jj];
                hs[off] = nh;
                sb[off] = siluf(nh);
            }
    } else {
        #pragma unroll
        for (int i = 0; i < 4; i++)
            #pragma unroll
            for (int jj = 0; jj < 8; jj++)
                g_table[(size_t)(row0 + ty * 4 + i) * FD + tx + 32 * jj] = acc[i][jj];
    }
}

__global__ __launch_bounds__(256, 1) void chain_kernel(
    const float* __restrict__ Wres1, const float* __restrict__ Wres2,
    const float* __restrict__ Wout, const float* __restrict__ Wv, int R) {
    extern __shared__ float sh[];
    const int tid = threadIdx.x;
    const int tx = tid & 31;
    const int ty = tid >> 5;
    const int row0 = blockIdx.x * CBM;
    float* hs = sh + SM_H;
    float* sb = sh + SM_S;

    // init: h = s_r * Wv (virtual y), sb = silu(h)
    #pragma unroll
    for (int i = 0; i < 4; i++) {
        float s = g_ns[row0 + ty * 4 + i];
        #pragma unroll
        for (int jj = 0; jj < 8; jj++) {
            int j = tx + 32 * jj;
            float v = s * Wv[j];
            hs[(ty * 4 + i) * HS + j] = v;
            sb[(ty * 4 + i) * HS + j] = siluf(v);
        }
    }
    __syncthreads();

    for (int r = 0; r < R; r++) {
        chain_stage(Wres1 + (size_t)r * FD * FD, sh, 0, row0);
        chain_stage(Wres2 + (size_t)r * FD * FD, sh, 1, row0);
    }
    chain_stage(Wout, sh, 2, row0);
}

// ======= Catmull-Rom interpolation: out[n,:] = G(s_n) from node table =========
__global__ __launch_bounds__(256) void interp_kernel(float* __restrict__ out, int M) {
    int atom = blockIdx.x * 8 + (threadIdx.x >> 5);
    int lane = threadIdx.x & 31;
    if (atom >= M) return;
    float u = (g_s[atom] - g_lo) * g_idelta;
    u = fminf(fmaxf(u, 0.f), (float)(NODES - 1));
    int i1 = (int)u;
    if (i1 > NODES - 1) i1 = NODES - 1;
    float t = u - (float)i1;
    int i0 = max(i1 - 1, 0);
    int i2 = min(i1 + 1, NODES - 1);
    int i3 = min(i1 + 2, NODES - 1);
    float t2 = t * t, t3 = t2 * t;
    float c0 = 0.5f * (-t3 + 2.f * t2 - t);
    float c1 = 0.5f * (3.f * t3 - 5.f * t2 + 2.f);
    float c2 = 0.5f * (-3.f * t3 + 4.f * t2 + t);
    float c3 = 0.5f * (t3 - t2);
    const float* p0 = g_table + (size_t)i0 * FD + lane * 8;
    const float* p1 = g_table + (size_t)i1 * FD + lane * 8;
    const float* p2 = g_table + (size_t)i2 * FD + lane * 8;
    const float* p3 = g_table + (size_t)i3 * FD + lane * 8;
    float* o = out + (size_t)atom * FD + lane * 8;
    #pragma unroll
    for (int h = 0; h < 2; h++) {
        float4 a = *(const float4*)(p0 + h * 4);
        float4 b = *(const float4*)(p1 + h * 4);
        float4 cc = *(const float4*)(p2 + h * 4);
        float4 d = *(const float4*)(p3 + h * 4);
        float4 r;
        r.x = c0 * a.x + c1 * b.x + c2 * cc.x + c3 * d.x;
        r.y = c0 * a.y + c1 * b.y + c2 * cc.y + c3 * d.y;
        r.z = c0 * a.z + c1 * b.z + c2 * cc.z + c3 * d.z;
        r.w = c0 * a.w + c1 * b.w + c2 * cc.w + c3 * d.w;
        *(float4*)(o + h * 4) = r;
    }
}

extern "C" void kernel_launch(void* const* d_in, const int* in_sizes, int n_in,
                              void* d_out, int out_size) {
    const float* x = (const float*)d_in[0];
    const float* E = (const float*)d_in[1];
    // d_in[2] = num_batch (unused; B from in_sizes[1])
    const int* seg = (const int*)d_in[3];   // int32 (JAX x64 disabled)
    const float* Wq = (const float*)d_in[4];
    const float* bq = (const float*)d_in[5];
    const float* Wk = (const float*)d_in[6];
    const float* Wv = (const float*)d_in[7];
    const float* Wres1 = (const float*)d_in[8];
    const float* Wres2 = (const float*)d_in[9];
    const float* Wout = (const float*)d_in[10];
    float* out = (float*)d_out;

    const int M = in_sizes[0] / FD;
    const int B = in_sizes[1];
    const int R = in_sizes[8] / (FD * FD);

    static int attr_done = 0;
    if (!attr_done) {
        cudaFuncSetAttribute(chain_kernel,
                             cudaFuncAttributeMaxDynamicSharedMemorySize, CHAIN_SMEM);
        attr_done = 1;
    }

    // ---- per-atom scalar s_n (exact) ----
    prep_w_kernel<<<1, 256>>>(Wq, bq, Wk);
    prep_batch_kernel<<<(B + 255) / 256, 256>>>(E, B);
    attn_kernel<<<(M + 7) / 8, 256>>>(x, seg, M);
    anorm_kernel<<<(B * 32 + 255) / 256, 256>>>(seg, M, B);
    s_minmax_kernel<<<(M + 255) / 256, 256>>>(seg, M);
    node_kernel<<<(NODES + 255) / 256, 256>>>();

    // ---- exact G at NODES points: ONE fused kernel, 148 CTAs, state in smem ----
    chain_kernel<<<NODES / CBM, 256, CHAIN_SMEM>>>(Wres1, Wres2, Wout, Wv, R);

    // ---- cubic interpolation to all atoms ----
    interp_kernel<<<(M + 7) / 8, 256>>>(out, M);
}